// round 2
// baseline (speedup 1.0000x reference)
#include <cuda_runtime.h>
#include <cuda_bf16.h>
#include <math.h>

// Problem constants (fixed by dataset: B=8, S=2048, H=8, D=64)
#define TT   16384          // B*S
#define EE   512            // hidden
#define HH   8
#define DD   64
#define SS   2048
#define BB   8
#define NT   64             // num_targets
#define N4   2048           // 4*H*D
#define ALPHA 0.125f        // 1/sqrt(64)

// Scratch (static device arrays; no runtime allocation allowed)
__device__ float g_xn  [TT * EE];    // 32 MB
__device__ float g_mix [TT * N4];    // 128 MB  (u|v|q|k)
__device__ float g_att [TT * EE];    // 32 MB
__device__ float g_par [TT * EE];    // 32 MB

// ---------------------------------------------------------------------------
// LayerNorm over 512 cols, one block (128 thr) per row, float4 per thread
// ---------------------------------------------------------------------------
__global__ void ln_in_kernel(const float* __restrict__ x,
                             const float* __restrict__ w,
                             const float* __restrict__ b,
                             float* __restrict__ out)
{
    int row = blockIdx.x;
    int tid = threadIdx.x;                       // 0..127
    const float4* xr = (const float4*)(x + (size_t)row * EE);
    float4 v = xr[tid];
    float s  = v.x + v.y + v.z + v.w;
    float s2 = v.x*v.x + v.y*v.y + v.z*v.z + v.w*v.w;
    #pragma unroll
    for (int off = 16; off; off >>= 1) {
        s  += __shfl_xor_sync(0xffffffffu, s,  off);
        s2 += __shfl_xor_sync(0xffffffffu, s2, off);
    }
    __shared__ float sb[4], sb2[4];
    int wid = tid >> 5, lane = tid & 31;
    if (lane == 0) { sb[wid] = s; sb2[wid] = s2; }
    __syncthreads();
    float tot = sb[0] + sb[1] + sb[2] + sb[3];
    float tot2 = sb2[0] + sb2[1] + sb2[2] + sb2[3];
    float mu  = tot * (1.0f / EE);
    float var = tot2 * (1.0f / EE) - mu * mu;
    float rstd = rsqrtf(var + 1e-5f);
    float4 w4 = ((const float4*)w)[tid];
    float4 b4 = ((const float4*)b)[tid];
    float4 o;
    o.x = (v.x - mu) * rstd * w4.x + b4.x;
    o.y = (v.y - mu) * rstd * w4.y + b4.y;
    o.z = (v.z - mu) * rstd * w4.z + b4.z;
    o.w = (v.w - mu) * rstd * w4.w + b4.w;
    ((float4*)(out + (size_t)row * EE))[tid] = o;
}

// LN(attn_out) * u  -> parallel    (u = g_mix[:, 0:512])
__global__ void ln_mul_kernel(const float* __restrict__ a,   // attn_out [T,512]
                              const float* __restrict__ w,
                              const float* __restrict__ b,
                              float* __restrict__ out)
{
    int row = blockIdx.x;
    int tid = threadIdx.x;
    const float4* xr = (const float4*)(a + (size_t)row * EE);
    float4 v = xr[tid];
    float s  = v.x + v.y + v.z + v.w;
    float s2 = v.x*v.x + v.y*v.y + v.z*v.z + v.w*v.w;
    #pragma unroll
    for (int off = 16; off; off >>= 1) {
        s  += __shfl_xor_sync(0xffffffffu, s,  off);
        s2 += __shfl_xor_sync(0xffffffffu, s2, off);
    }
    __shared__ float sb[4], sb2[4];
    int wid = tid >> 5, lane = tid & 31;
    if (lane == 0) { sb[wid] = s; sb2[wid] = s2; }
    __syncthreads();
    float tot = sb[0] + sb[1] + sb[2] + sb[3];
    float tot2 = sb2[0] + sb2[1] + sb2[2] + sb2[3];
    float mu  = tot * (1.0f / EE);
    float var = tot2 * (1.0f / EE) - mu * mu;
    float rstd = rsqrtf(var + 1e-5f);
    float4 w4 = ((const float4*)w)[tid];
    float4 b4 = ((const float4*)b)[tid];
    float4 u4 = ((const float4*)(g_mix + (size_t)row * N4))[tid];  // u block
    float4 o;
    o.x = u4.x * ((v.x - mu) * rstd * w4.x + b4.x);
    o.y = u4.y * ((v.y - mu) * rstd * w4.y + b4.y);
    o.z = u4.z * ((v.z - mu) * rstd * w4.z + b4.z);
    o.w = u4.w * ((v.w - mu) * rstd * w4.w + b4.w);
    ((float4*)(out + (size_t)row * EE))[tid] = o;
}

// ---------------------------------------------------------------------------
// SGEMM: C[M,N] = f(A[M,K] @ B[K,N] + bias) (+ res)
// 64x64 block tile, 4x4 per thread, 256 threads, BK=16
// ---------------------------------------------------------------------------
template<bool SILU, bool RES>
__global__ void sgemm_kernel(const float* __restrict__ A,
                             const float* __restrict__ B,
                             const float* __restrict__ bias,
                             const float* __restrict__ res,
                             float* __restrict__ C,
                             int M, int N, int K)
{
    __shared__ float As[16][64];
    __shared__ float Bs[16][64];

    int bm = blockIdx.y * 64;
    int bn = blockIdx.x * 64;
    int tid = threadIdx.x;
    int ty = tid >> 4, tx = tid & 15;

    float acc[4][4] = {};

    for (int k0 = 0; k0 < K; k0 += 16) {
        // A tile: As[k][m] = A[bm+m][k0+k]
        #pragma unroll
        for (int p = 0; p < 4; p++) {
            int m = (tid >> 4) + p * 16;
            int k = tid & 15;
            As[k][m] = A[(size_t)(bm + m) * K + k0 + k];
        }
        // B tile: Bs[k][n] = B[k0+k][bn+n]
        #pragma unroll
        for (int p = 0; p < 4; p++) {
            int k = (tid >> 6) + p * 4;
            int n = tid & 63;
            Bs[k][n] = B[(size_t)(k0 + k) * N + bn + n];
        }
        __syncthreads();
        #pragma unroll
        for (int k = 0; k < 16; k++) {
            float a[4], bb[4];
            #pragma unroll
            for (int i = 0; i < 4; i++) a[i]  = As[k][ty * 4 + i];
            #pragma unroll
            for (int j = 0; j < 4; j++) bb[j] = Bs[k][tx * 4 + j];
            #pragma unroll
            for (int i = 0; i < 4; i++)
                #pragma unroll
                for (int j = 0; j < 4; j++)
                    acc[i][j] = fmaf(a[i], bb[j], acc[i][j]);
        }
        __syncthreads();
    }

    #pragma unroll
    for (int i = 0; i < 4; i++) {
        int m = bm + ty * 4 + i;
        #pragma unroll
        for (int j = 0; j < 4; j++) {
            int n = bn + tx * 4 + j;
            float v = acc[i][j];
            if (bias) v += bias[n];
            if (SILU) v = v / (1.0f + __expf(-v));
            if (RES)  v += res[(size_t)m * N + n];
            C[(size_t)m * N + n] = v;
        }
    }
}

// ---------------------------------------------------------------------------
// SiLU attention: per (b,h), streaming over key tiles (causal + target mask)
// attn_out[b,s,h,:] = sum_j silu(alpha * q.k)/S * v
// ---------------------------------------------------------------------------
__global__ void attn_kernel()
{
    extern __shared__ float sm[];
    float* qT = sm;                    // [64][65]  qT[d*65+i]
    float* kT = qT + 64 * 65;          // [64][65]  kT[d*65+j]
    float* ss = kT + 64 * 65;          // [64][65]  ss[i*65+j]
    float* vS = ss + 64 * 65;          // [64][64]  vS[j*64+d]

    int bi = blockIdx.x;               // query tile (0..31)
    int h  = blockIdx.y;
    int b  = blockIdx.z;
    int tid = threadIdx.x;
    int ty = tid >> 4, tx = tid & 15;

    const int qoff = 1024 + h * 64;    // q block in g_mix
    const int koff = 1536 + h * 64;
    const int voff = 512  + h * 64;
    const int ibase = bi * 64;
    const size_t rowb = (size_t)b * SS;

    // load q tile (transposed)
    for (int idx = tid; idx < 4096; idx += 256) {
        int i = idx >> 6, d = idx & 63;
        qT[d * 65 + i] = g_mix[(rowb + ibase + i) * N4 + qoff + d];
    }

    float o[4][4] = {};
    const float invS = 1.0f / (float)SS;

    for (int jt = 0; jt <= bi; jt++) {
        int jbase = jt * 64;
        __syncthreads();   // protect kT/vS/ss from previous iteration consumers
        for (int idx = tid; idx < 4096; idx += 256) {
            int j = idx >> 6, d = idx & 63;
            size_t r = (rowb + jbase + j) * N4;
            kT[d * 65 + j] = g_mix[r + koff + d];
            vS[j * 64 + d] = g_mix[r + voff + d];
        }
        __syncthreads();

        // s = q @ k^T  (64x64x64)
        float acc[4][4] = {};
        #pragma unroll
        for (int d = 0; d < 64; d++) {
            float a[4], bb[4];
            #pragma unroll
            for (int i = 0; i < 4; i++) a[i]  = qT[d * 65 + ty * 4 + i];
            #pragma unroll
            for (int j = 0; j < 4; j++) bb[j] = kT[d * 65 + tx * 4 + j];
            #pragma unroll
            for (int i = 0; i < 4; i++)
                #pragma unroll
                for (int j = 0; j < 4; j++)
                    acc[i][j] = fmaf(a[i], bb[j], acc[i][j]);
        }

        // mask + silu -> ss
        #pragma unroll
        for (int i = 0; i < 4; i++) {
            int gi = ibase + ty * 4 + i;
            #pragma unroll
            for (int j = 0; j < 4; j++) {
                int gj = jbase + tx * 4 + j;
                float z = acc[i][j] * ALPHA;
                float sv = z / (1.0f + __expf(-z)) * invS;
                bool valid = (gj <= gi) && ((gj < SS - NT) || (gj == gi));
                ss[(ty * 4 + i) * 65 + (tx * 4 + j)] = valid ? sv : 0.0f;
            }
        }
        __syncthreads();

        // o += ss @ v  (64x64x64)
        #pragma unroll
        for (int jk = 0; jk < 64; jk++) {
            float a[4], bb[4];
            #pragma unroll
            for (int i = 0; i < 4; i++) a[i]  = ss[(ty * 4 + i) * 65 + jk];
            #pragma unroll
            for (int j = 0; j < 4; j++) bb[j] = vS[jk * 64 + tx * 4 + j];
            #pragma unroll
            for (int i = 0; i < 4; i++)
                #pragma unroll
                for (int j = 0; j < 4; j++)
                    o[i][j] = fmaf(a[i], bb[j], o[i][j]);
        }
    }

    // write attn_out
    #pragma unroll
    for (int i = 0; i < 4; i++) {
        size_t row = rowb + ibase + ty * 4 + i;
        #pragma unroll
        for (int j = 0; j < 4; j++) {
            g_att[row * EE + h * 64 + tx * 4 + j] = o[i][j];
        }
    }
}

// ---------------------------------------------------------------------------
extern "C" void kernel_launch(void* const* d_in, const int* in_sizes, int n_in,
                              void* d_out, int out_size)
{
    const float* x       = (const float*)d_in[0];
    const float* w_uvqk  = (const float*)d_in[1];
    const float* b_uvqk  = (const float*)d_in[2];
    const float* ln_in_w = (const float*)d_in[3];
    const float* ln_in_b = (const float*)d_in[4];
    const float* ln_o_w  = (const float*)d_in[5];
    const float* ln_o_b  = (const float*)d_in[6];
    const float* w_proj  = (const float*)d_in[7];
    float* out = (float*)d_out;

    float *xn, *mix, *att, *par;
    cudaGetSymbolAddress((void**)&xn,  g_xn);
    cudaGetSymbolAddress((void**)&mix, g_mix);
    cudaGetSymbolAddress((void**)&att, g_att);
    cudaGetSymbolAddress((void**)&par, g_par);

    // 1) input LN
    ln_in_kernel<<<TT, 128>>>(x, ln_in_w, ln_in_b, xn);

    // 2) mixed = silu(xn @ w_uvqk + b)
    {
        dim3 grid(N4 / 64, TT / 64);
        sgemm_kernel<true, false><<<grid, 256>>>(xn, w_uvqk, b_uvqk, nullptr,
                                                 mix, TT, N4, EE);
    }

    // 3) attention
    {
        static const size_t smem = (3 * 64 * 65 + 64 * 64) * sizeof(float);
        cudaFuncSetAttribute(attn_kernel,
                             cudaFuncAttributeMaxDynamicSharedMemorySize,
                             (int)smem);
        dim3 grid(SS / 64, HH, BB);
        attn_kernel<<<grid, 256, smem>>>();
    }

    // 4) parallel = u * LN(attn_out)
    ln_mul_kernel<<<TT, 128>>>(att, ln_o_w, ln_o_b, par);

    // 5) out = parallel @ w_proj + x
    {
        dim3 grid(EE / 64, TT / 64);
        sgemm_kernel<false, true><<<grid, 256>>>(par, w_proj, nullptr, x,
                                                 out, TT, EE, EE);
    }
}

// round 6
// speedup vs baseline: 2.9420x; 2.9420x over previous
#include <cuda_runtime.h>
#include <math.h>
#include <stdint.h>

// Problem constants (fixed: B=8, S=2048, H=8, D=64)
#define TT   16384
#define EE   512
#define HH   8
#define SS   2048
#define BB   8
#define NT   64
#define N4   2048
#define ALPHA 0.125f

// Scratch
__device__ float g_xn  [TT * EE];
__device__ float g_mix [TT * N4];
__device__ float g_att [TT * EE];
__device__ float g_par [TT * EE];
__device__ float g_wuT [N4 * EE];
__device__ float g_wpT [EE * EE];

// ---------------------------------------------------------------------------
__device__ __forceinline__ uint32_t smem_u32(const void* p) {
    uint32_t a;
    asm("{ .reg .u64 t; cvta.to.shared.u64 t, %1; cvt.u32.u64 %0, t; }"
        : "=r"(a) : "l"(p));
    return a;
}
__device__ __forceinline__ float tf32_rna(float x) {
    uint32_t u = __float_as_uint(x);
    asm("cvt.rna.tf32.f32 %0, %1;" : "=r"(u) : "r"(u));
    return __uint_as_float(u);
}
// D = A(16x8) @ B(8x8) + D, tf32 inputs, f32 accum
__device__ __forceinline__ void mma_tf32(float* c, const uint32_t* a, const uint32_t* b) {
    asm volatile(
        "mma.sync.aligned.m16n8k8.row.col.f32.tf32.tf32.f32 "
        "{%0,%1,%2,%3}, {%4,%5,%6,%7}, {%8,%9}, {%0,%1,%2,%3};"
        : "+f"(c[0]), "+f"(c[1]), "+f"(c[2]), "+f"(c[3])
        : "r"(a[0]), "r"(a[1]), "r"(a[2]), "r"(a[3]), "r"(b[0]), "r"(b[1]));
}
#define CP_ASYNC16(s, g) asm volatile("cp.async.cg.shared.global [%0], [%1], 16;" :: "r"(s), "l"(g))
#define CP_COMMIT()      asm volatile("cp.async.commit_group;")
#define CP_WAIT1()       asm volatile("cp.async.wait_group 1;" ::: "memory")
#define CP_WAIT0()       asm volatile("cp.async.wait_group 0;" ::: "memory")

// ---------------------------------------------------------------------------
// Weight transpose + tf32 rounding: dst[n][k] = rna(src[k][n])
// ---------------------------------------------------------------------------
__global__ void transpose_kernel(const float* __restrict__ src,
                                 float* __restrict__ dst, int K, int N)
{
    __shared__ float t[32][33];
    int n0 = blockIdx.x * 32, k0 = blockIdx.y * 32;
    int tx = threadIdx.x, ty = threadIdx.y;
    #pragma unroll
    for (int j = 0; j < 4; j++)
        t[ty + j * 8][tx] = src[(size_t)(k0 + ty + j * 8) * N + n0 + tx];
    __syncthreads();
    #pragma unroll
    for (int j = 0; j < 4; j++)
        dst[(size_t)(n0 + ty + j * 8) * K + k0 + tx] = tf32_rna(t[tx][ty + j * 8]);
}

// ---------------------------------------------------------------------------
// LayerNorm kernels (tf32-rounded outputs — they feed tensor-core GEMMs)
// ---------------------------------------------------------------------------
__global__ void ln_in_kernel(const float* __restrict__ x,
                             const float* __restrict__ w,
                             const float* __restrict__ b,
                             float* __restrict__ out)
{
    int row = blockIdx.x;
    int tid = threadIdx.x;
    const float4* xr = (const float4*)(x + (size_t)row * EE);
    float4 v = xr[tid];
    float s  = v.x + v.y + v.z + v.w;
    float s2 = v.x*v.x + v.y*v.y + v.z*v.z + v.w*v.w;
    #pragma unroll
    for (int off = 16; off; off >>= 1) {
        s  += __shfl_xor_sync(0xffffffffu, s,  off);
        s2 += __shfl_xor_sync(0xffffffffu, s2, off);
    }
    __shared__ float sb[4], sb2[4];
    int wid = tid >> 5, lane = tid & 31;
    if (lane == 0) { sb[wid] = s; sb2[wid] = s2; }
    __syncthreads();
    float tot  = sb[0] + sb[1] + sb[2] + sb[3];
    float tot2 = sb2[0] + sb2[1] + sb2[2] + sb2[3];
    float mu  = tot * (1.0f / EE);
    float var = tot2 * (1.0f / EE) - mu * mu;
    float rstd = rsqrtf(var + 1e-5f);
    float4 w4 = ((const float4*)w)[tid];
    float4 b4 = ((const float4*)b)[tid];
    float4 o;
    o.x = tf32_rna((v.x - mu) * rstd * w4.x + b4.x);
    o.y = tf32_rna((v.y - mu) * rstd * w4.y + b4.y);
    o.z = tf32_rna((v.z - mu) * rstd * w4.z + b4.z);
    o.w = tf32_rna((v.w - mu) * rstd * w4.w + b4.w);
    ((float4*)(out + (size_t)row * EE))[tid] = o;
}

__global__ void ln_mul_kernel(const float* __restrict__ a,
                              const float* __restrict__ w,
                              const float* __restrict__ b,
                              float* __restrict__ out)
{
    int row = blockIdx.x;
    int tid = threadIdx.x;
    const float4* xr = (const float4*)(a + (size_t)row * EE);
    float4 v = xr[tid];
    float s  = v.x + v.y + v.z + v.w;
    float s2 = v.x*v.x + v.y*v.y + v.z*v.z + v.w*v.w;
    #pragma unroll
    for (int off = 16; off; off >>= 1) {
        s  += __shfl_xor_sync(0xffffffffu, s,  off);
        s2 += __shfl_xor_sync(0xffffffffu, s2, off);
    }
    __shared__ float sb[4], sb2[4];
    int wid = tid >> 5, lane = tid & 31;
    if (lane == 0) { sb[wid] = s; sb2[wid] = s2; }
    __syncthreads();
    float tot  = sb[0] + sb[1] + sb[2] + sb[3];
    float tot2 = sb2[0] + sb2[1] + sb2[2] + sb2[3];
    float mu  = tot * (1.0f / EE);
    float var = tot2 * (1.0f / EE) - mu * mu;
    float rstd = rsqrtf(var + 1e-5f);
    float4 w4 = ((const float4*)w)[tid];
    float4 b4 = ((const float4*)b)[tid];
    float4 u4 = ((const float4*)(g_mix + (size_t)row * N4))[tid];
    float4 o;
    o.x = tf32_rna(u4.x * ((v.x - mu) * rstd * w4.x + b4.x));
    o.y = tf32_rna(u4.y * ((v.y - mu) * rstd * w4.y + b4.y));
    o.z = tf32_rna(u4.z * ((v.z - mu) * rstd * w4.z + b4.z));
    o.w = tf32_rna(u4.w * ((v.w - mu) * rstd * w4.w + b4.w));
    ((float4*)(out + (size_t)row * EE))[tid] = o;
}

// ---------------------------------------------------------------------------
// mma.sync tf32 GEMM: C[M,N] = f(A @ Bt^T + bias) (+res)
//   A [M,K] K-major, Bt [N,K] K-major.
//   128x128 tile, BK=32, 8 warps (2x4), 64x32 per warp, double-buffered cp.async
// ---------------------------------------------------------------------------
#define ASTRIDE 36
#define AB0 0
#define AB1 4608
#define BB0 9216
#define BB1 13824
#define GEMM_SMEM (18432 * 4)

template<bool SILU, bool RES>
__global__ void __launch_bounds__(256)
gemm_mma(const float* __restrict__ A, const float* __restrict__ Bt,
         const float* __restrict__ bias, const float* __restrict__ res,
         float* __restrict__ C, int M, int N, int K)
{
    extern __shared__ float sm[];
    uint32_t sbase = smem_u32(sm);
    int tid = threadIdx.x;
    int wid = tid >> 5, lane = tid & 31;
    int g = lane >> 2, t = lane & 3;
    int wm = wid >> 2, wn = wid & 3;
    int bm = blockIdx.y * 128, bn = blockIdx.x * 128;
    const int NC = K >> 5;

    float c[4][4][4];
    #pragma unroll
    for (int i = 0; i < 4; i++)
        #pragma unroll
        for (int j = 0; j < 4; j++)
            #pragma unroll
            for (int e = 0; e < 4; e++) c[i][j][e] = 0.0f;

    auto load_tile = [&](int koff, int buf) {
        uint32_t ab = sbase + (buf ? AB1 : AB0) * 4;
        uint32_t bb = sbase + (buf ? BB1 : BB0) * 4;
        #pragma unroll
        for (int p = 0; p < 4; p++) {
            int idx = tid + p * 256;
            int row = idx >> 3, q = idx & 7;
            CP_ASYNC16(ab + row * 144 + q * 16,
                       A + (size_t)(bm + row) * K + koff + q * 4);
        }
        #pragma unroll
        for (int p = 0; p < 4; p++) {
            int idx = tid + p * 256;
            int row = idx >> 3, q = idx & 7;
            CP_ASYNC16(bb + row * 144 + q * 16,
                       Bt + (size_t)(bn + row) * K + koff + q * 4);
        }
        CP_COMMIT();
    };

    load_tile(0, 0);

    for (int i = 0; i < NC; i++) {
        if (i + 1 < NC) { load_tile((i + 1) << 5, (i + 1) & 1); CP_WAIT1(); }
        else            { CP_WAIT0(); }
        __syncthreads();

        const float* As = sm + ((i & 1) ? AB1 : AB0);
        const float* Bs = sm + ((i & 1) ? BB1 : BB0);

        #pragma unroll
        for (int k8 = 0; k8 < 4; k8++) {
            int kk = k8 * 8;
            uint32_t a[4][4], b[4][2];
            #pragma unroll
            for (int mt = 0; mt < 4; mt++) {
                const float* ap = As + (wm * 64 + mt * 16 + g) * ASTRIDE + kk + t;
                a[mt][0] = __float_as_uint(ap[0]);
                a[mt][1] = __float_as_uint(ap[8 * ASTRIDE]);
                a[mt][2] = __float_as_uint(ap[4]);
                a[mt][3] = __float_as_uint(ap[8 * ASTRIDE + 4]);
            }
            #pragma unroll
            for (int nt = 0; nt < 4; nt++) {
                const float* bp = Bs + (wn * 32 + nt * 8 + g) * ASTRIDE + kk + t;
                b[nt][0] = __float_as_uint(bp[0]);
                b[nt][1] = __float_as_uint(bp[4]);
            }
            #pragma unroll
            for (int mt = 0; mt < 4; mt++)
                #pragma unroll
                for (int nt = 0; nt < 4; nt++)
                    mma_tf32(c[mt][nt], a[mt], b[nt]);
        }
        __syncthreads();
    }

    // epilogue: register -> global (float2 pairs), bias/silu/residual fused
    #pragma unroll
    for (int mt = 0; mt < 4; mt++) {
        int r0 = bm + wm * 64 + mt * 16 + g;
        #pragma unroll
        for (int nt = 0; nt < 4; nt++) {
            int col = bn + wn * 32 + nt * 8 + 2 * t;
            float bx = 0.f, by = 0.f;
            if (bias) { bx = __ldg(bias + col); by = __ldg(bias + col + 1); }
            #pragma unroll
            for (int half = 0; half < 2; half++) {
                int r = r0 + half * 8;
                float vx = c[mt][nt][half * 2 + 0] + bx;
                float vy = c[mt][nt][half * 2 + 1] + by;
                if (SILU) {
                    vx = vx / (1.0f + __expf(-vx));
                    vy = vy / (1.0f + __expf(-vy));
                }
                if (RES) {
                    float2 rr = *(const float2*)(res + (size_t)r * N + col);
                    vx += rr.x; vy += rr.y;
                }
                *(float2*)(C + (size_t)r * N + col) = make_float2(vx, vy);
            }
        }
    }
}

// ---------------------------------------------------------------------------
// SiLU attention with mma.sync tf32.
// Computes S^T = K @ Q^T (so K,V load row-major), then O = P @ V.
// smem: Ks[64][68], QT[64][72], Vs[64][72], Ps[64][68]
// ---------------------------------------------------------------------------
#define KS_OFF 0
#define QT_OFF 4352
#define VS_OFF 8960
#define PS_OFF 13568
#define ATT_SMEM (17920 * 4)

__global__ void __launch_bounds__(256) attn_mma()
{
    extern __shared__ float sm[];
    int bi = blockIdx.x, h = blockIdx.y, b = blockIdx.z;
    int tid = threadIdx.x, wid = tid >> 5, lane = tid & 31;
    int g = lane >> 2, t = lane & 3;
    int wj = wid >> 1, wi = wid & 1;      // QK: j-tile / i-half. PV: i-tile / d-half.
    const int qoff = 1024 + h * 64;
    const int koff = 1536 + h * 64;
    const int voff = 512  + h * 64;
    const int ibase = bi * 64;
    const size_t rowb = (size_t)b * SS;
    const float invS = 1.0f / (float)SS;

    // Q^T (transposed store: conflicts OK, once per CTA)
    for (int idx = tid; idx < 4096; idx += 256) {
        int i = idx >> 6, d = idx & 63;
        sm[QT_OFF + d * 72 + i] =
            tf32_rna(g_mix[(rowb + ibase + i) * N4 + qoff + d]);
    }

    float o[4][4];
    #pragma unroll
    for (int nt = 0; nt < 4; nt++)
        #pragma unroll
        for (int e = 0; e < 4; e++) o[nt][e] = 0.0f;

    for (int jt = 0; jt <= bi; jt++) {
        int jbase = jt * 64;
        __syncthreads();    // prev PV done with Vs/Ps; Q^T visible on jt=0
        for (int idx = tid; idx < 4096; idx += 256) {
            int j = idx >> 6, d = idx & 63;
            size_t r = (rowb + jbase + j) * N4;
            sm[KS_OFF + j * 68 + d] = tf32_rna(g_mix[r + koff + d]);
            sm[VS_OFF + j * 72 + d] = tf32_rna(g_mix[r + voff + d]);
        }
        __syncthreads();

        // S^T tile: rows j (wj*16), cols i (wi*32, 4 n-tiles)
        float c[4][4];
        #pragma unroll
        for (int nt = 0; nt < 4; nt++)
            #pragma unroll
            for (int e = 0; e < 4; e++) c[nt][e] = 0.0f;

        #pragma unroll
        for (int k8 = 0; k8 < 8; k8++) {
            int kk = k8 * 8;
            uint32_t a[4], bfr[4][2];
            const float* ap = sm + KS_OFF + (wj * 16 + g) * 68 + kk + t;
            a[0] = __float_as_uint(ap[0]);
            a[1] = __float_as_uint(ap[8 * 68]);
            a[2] = __float_as_uint(ap[4]);
            a[3] = __float_as_uint(ap[8 * 68 + 4]);
            #pragma unroll
            for (int nt = 0; nt < 4; nt++) {
                const float* bp = sm + QT_OFF + (kk + t) * 72 + wi * 32 + nt * 8 + g;
                bfr[nt][0] = __float_as_uint(bp[0]);
                bfr[nt][1] = __float_as_uint(bp[4 * 72]);
            }
            #pragma unroll
            for (int nt = 0; nt < 4; nt++)
                mma_tf32(c[nt], a, bfr[nt]);
        }

        // silu + mask (mask only needed on diagonal tile), store P[i][j]
        bool diag = (jt == bi);
        #pragma unroll
        for (int nt = 0; nt < 4; nt++) {
            #pragma unroll
            for (int e = 0; e < 4; e++) {
                int jl = wj * 16 + g + ((e >> 1) * 8);
                int il = wi * 32 + nt * 8 + 2 * t + (e & 1);
                float z = c[nt][e] * ALPHA;
                float sv = z / (1.0f + __expf(-z)) * invS;
                if (diag) {
                    int gj = jbase + jl, gi = ibase + il;
                    bool valid = (gj <= gi) && ((gj < SS - NT) || (gi == gj));
                    sv = valid ? sv : 0.0f;
                }
                sm[PS_OFF + il * 68 + jl] = tf32_rna(sv);
            }
        }
        __syncthreads();

        // O += P @ V : rows i (wj*16), cols d (wi*32, 4 n-tiles), k = j (64)
        #pragma unroll
        for (int k8 = 0; k8 < 8; k8++) {
            int kk = k8 * 8;
            uint32_t a[4], bfr[4][2];
            const float* ap = sm + PS_OFF + (wj * 16 + g) * 68 + kk + t;
            a[0] = __float_as_uint(ap[0]);
            a[1] = __float_as_uint(ap[8 * 68]);
            a[2] = __float_as_uint(ap[4]);
            a[3] = __float_as_uint(ap[8 * 68 + 4]);
            #pragma unroll
            for (int nt = 0; nt < 4; nt++) {
                const float* bp = sm + VS_OFF + (kk + t) * 72 + wi * 32 + nt * 8 + g;
                bfr[nt][0] = __float_as_uint(bp[0]);
                bfr[nt][1] = __float_as_uint(bp[4 * 72]);
            }
            #pragma unroll
            for (int nt = 0; nt < 4; nt++)
                mma_tf32(o[nt], a, bfr[nt]);
        }
    }

    // write attn_out
    #pragma unroll
    for (int nt = 0; nt < 4; nt++) {
        int col = h * 64 + wi * 32 + nt * 8 + 2 * t;
        #pragma unroll
        for (int half = 0; half < 2; half++) {
            size_t r = rowb + ibase + wj * 16 + g + half * 8;
            *(float2*)(g_att + r * EE + col) =
                make_float2(o[nt][half * 2 + 0], o[nt][half * 2 + 1]);
        }
    }
}

// ---------------------------------------------------------------------------
extern "C" void kernel_launch(void* const* d_in, const int* in_sizes, int n_in,
                              void* d_out, int out_size)
{
    const float* x       = (const float*)d_in[0];
    const float* w_uvqk  = (const float*)d_in[1];
    const float* b_uvqk  = (const float*)d_in[2];
    const float* ln_in_w = (const float*)d_in[3];
    const float* ln_in_b = (const float*)d_in[4];
    const float* ln_o_w  = (const float*)d_in[5];
    const float* ln_o_b  = (const float*)d_in[6];
    const float* w_proj  = (const float*)d_in[7];
    float* out = (float*)d_out;

    float *xn, *mix, *att, *par, *wuT, *wpT;
    cudaGetSymbolAddress((void**)&xn,  g_xn);
    cudaGetSymbolAddress((void**)&mix, g_mix);
    cudaGetSymbolAddress((void**)&att, g_att);
    cudaGetSymbolAddress((void**)&par, g_par);
    cudaGetSymbolAddress((void**)&wuT, g_wuT);
    cudaGetSymbolAddress((void**)&wpT, g_wpT);

    cudaFuncSetAttribute(gemm_mma<true, false>,
                         cudaFuncAttributeMaxDynamicSharedMemorySize, GEMM_SMEM);
    cudaFuncSetAttribute(gemm_mma<false, true>,
                         cudaFuncAttributeMaxDynamicSharedMemorySize, GEMM_SMEM);
    cudaFuncSetAttribute(attn_mma,
                         cudaFuncAttributeMaxDynamicSharedMemorySize, ATT_SMEM);

    // weight transposes (tf32-rounded)
    {
        dim3 b32(32, 8);
        transpose_kernel<<<dim3(N4 / 32, EE / 32), b32>>>(w_uvqk, wuT, EE, N4);
        transpose_kernel<<<dim3(EE / 32, EE / 32), b32>>>(w_proj, wpT, EE, EE);
    }

    // 1) input LN
    ln_in_kernel<<<TT, 128>>>(x, ln_in_w, ln_in_b, xn);

    // 2) mixed = silu(xn @ w_uvqk + b)
    {
        dim3 grid(N4 / 128, TT / 128);
        gemm_mma<true, false><<<grid, 256, GEMM_SMEM>>>(xn, wuT, b_uvqk, nullptr,
                                                        mix, TT, N4, EE);
    }

    // 3) attention
    {
        dim3 grid(SS / 64, HH, BB);
        attn_mma<<<grid, 256, ATT_SMEM>>>();
    }

    // 4) parallel = u * LN(attn_out)
    ln_mul_kernel<<<TT, 128>>>(att, ln_o_w, ln_o_b, par);

    // 5) out = parallel @ w_proj + x
    {
        dim3 grid(EE / 128, TT / 128);
        gemm_mma<false, true><<<grid, 256, GEMM_SMEM>>>(par, wpT, nullptr, x,
                                                        out, TT, EE, EE);
    }
}

// round 7
// speedup vs baseline: 3.4306x; 1.1661x over previous
#include <cuda_runtime.h>
#include <math.h>
#include <stdint.h>

// Problem constants (fixed: B=8, S=2048, H=8, D=64)
#define TT   16384
#define EE   512
#define HH   8
#define SS   2048
#define BB   8
#define NT   64
#define N4   2048
#define ALPHA 0.125f

// Scratch
__device__ float g_xn  [TT * EE];
__device__ float g_mix [TT * N4];
__device__ float g_att [TT * EE];
__device__ float g_par [TT * EE];
__device__ float g_wuT [N4 * EE];
__device__ float g_wpT [EE * EE];

// ---------------------------------------------------------------------------
__device__ __forceinline__ uint32_t smem_u32(const void* p) {
    uint32_t a;
    asm("{ .reg .u64 t; cvta.to.shared.u64 t, %1; cvt.u32.u64 %0, t; }"
        : "=r"(a) : "l"(p));
    return a;
}
__device__ __forceinline__ float tf32_rna(float x) {
    uint32_t u = __float_as_uint(x);
    asm("cvt.rna.tf32.f32 %0, %1;" : "=r"(u) : "r"(u));
    return __uint_as_float(u);
}
// D = A(16x8) @ B(8x8) + D, tf32 inputs, f32 accum
__device__ __forceinline__ void mma_tf32(float* c, const uint32_t* a, const uint32_t* b) {
    asm volatile(
        "mma.sync.aligned.m16n8k8.row.col.f32.tf32.tf32.f32 "
        "{%0,%1,%2,%3}, {%4,%5,%6,%7}, {%8,%9}, {%0,%1,%2,%3};"
        : "+f"(c[0]), "+f"(c[1]), "+f"(c[2]), "+f"(c[3])
        : "r"(a[0]), "r"(a[1]), "r"(a[2]), "r"(a[3]), "r"(b[0]), "r"(b[1]));
}
#define CP_ASYNC16(s, g) asm volatile("cp.async.cg.shared.global [%0], [%1], 16;" :: "r"(s), "l"(g))
#define CP_COMMIT()      asm volatile("cp.async.commit_group;")
#define CP_WAIT1()       asm volatile("cp.async.wait_group 1;" ::: "memory")
#define CP_WAIT0()       asm volatile("cp.async.wait_group 0;" ::: "memory")

// ---------------------------------------------------------------------------
// Weight transpose + tf32 rounding: dst[n][k] = rna(src[k][n])
// ---------------------------------------------------------------------------
__global__ void transpose_kernel(const float* __restrict__ src,
                                 float* __restrict__ dst, int K, int N)
{
    __shared__ float t[32][33];
    int n0 = blockIdx.x * 32, k0 = blockIdx.y * 32;
    int tx = threadIdx.x, ty = threadIdx.y;
    #pragma unroll
    for (int j = 0; j < 4; j++)
        t[ty + j * 8][tx] = src[(size_t)(k0 + ty + j * 8) * N + n0 + tx];
    __syncthreads();
    #pragma unroll
    for (int j = 0; j < 4; j++)
        dst[(size_t)(n0 + ty + j * 8) * K + k0 + tx] = tf32_rna(t[tx][ty + j * 8]);
}

// ---------------------------------------------------------------------------
// LayerNorm kernels (tf32-rounded outputs — they feed tensor-core GEMMs)
// ---------------------------------------------------------------------------
__global__ void ln_in_kernel(const float* __restrict__ x,
                             const float* __restrict__ w,
                             const float* __restrict__ b,
                             float* __restrict__ out)
{
    int row = blockIdx.x;
    int tid = threadIdx.x;
    const float4* xr = (const float4*)(x + (size_t)row * EE);
    float4 v = xr[tid];
    float s  = v.x + v.y + v.z + v.w;
    float s2 = v.x*v.x + v.y*v.y + v.z*v.z + v.w*v.w;
    #pragma unroll
    for (int off = 16; off; off >>= 1) {
        s  += __shfl_xor_sync(0xffffffffu, s,  off);
        s2 += __shfl_xor_sync(0xffffffffu, s2, off);
    }
    __shared__ float sb[4], sb2[4];
    int wid = tid >> 5, lane = tid & 31;
    if (lane == 0) { sb[wid] = s; sb2[wid] = s2; }
    __syncthreads();
    float tot  = sb[0] + sb[1] + sb[2] + sb[3];
    float tot2 = sb2[0] + sb2[1] + sb2[2] + sb2[3];
    float mu  = tot * (1.0f / EE);
    float var = tot2 * (1.0f / EE) - mu * mu;
    float rstd = rsqrtf(var + 1e-5f);
    float4 w4 = ((const float4*)w)[tid];
    float4 b4 = ((const float4*)b)[tid];
    float4 o;
    o.x = tf32_rna((v.x - mu) * rstd * w4.x + b4.x);
    o.y = tf32_rna((v.y - mu) * rstd * w4.y + b4.y);
    o.z = tf32_rna((v.z - mu) * rstd * w4.z + b4.z);
    o.w = tf32_rna((v.w - mu) * rstd * w4.w + b4.w);
    ((float4*)(out + (size_t)row * EE))[tid] = o;
}

__global__ void ln_mul_kernel(const float* __restrict__ a,
                              const float* __restrict__ w,
                              const float* __restrict__ b,
                              float* __restrict__ out)
{
    int row = blockIdx.x;
    int tid = threadIdx.x;
    const float4* xr = (const float4*)(a + (size_t)row * EE);
    float4 v = xr[tid];
    float s  = v.x + v.y + v.z + v.w;
    float s2 = v.x*v.x + v.y*v.y + v.z*v.z + v.w*v.w;
    #pragma unroll
    for (int off = 16; off; off >>= 1) {
        s  += __shfl_xor_sync(0xffffffffu, s,  off);
        s2 += __shfl_xor_sync(0xffffffffu, s2, off);
    }
    __shared__ float sb[4], sb2[4];
    int wid = tid >> 5, lane = tid & 31;
    if (lane == 0) { sb[wid] = s; sb2[wid] = s2; }
    __syncthreads();
    float tot  = sb[0] + sb[1] + sb[2] + sb[3];
    float tot2 = sb2[0] + sb2[1] + sb2[2] + sb2[3];
    float mu  = tot * (1.0f / EE);
    float var = tot2 * (1.0f / EE) - mu * mu;
    float rstd = rsqrtf(var + 1e-5f);
    float4 w4 = ((const float4*)w)[tid];
    float4 b4 = ((const float4*)b)[tid];
    float4 u4 = ((const float4*)(g_mix + (size_t)row * N4))[tid];
    float4 o;
    o.x = tf32_rna(u4.x * ((v.x - mu) * rstd * w4.x + b4.x));
    o.y = tf32_rna(u4.y * ((v.y - mu) * rstd * w4.y + b4.y));
    o.z = tf32_rna(u4.z * ((v.z - mu) * rstd * w4.z + b4.z));
    o.w = tf32_rna(u4.w * ((v.w - mu) * rstd * w4.w + b4.w));
    ((float4*)(out + (size_t)row * EE))[tid] = o;
}

// ---------------------------------------------------------------------------
// mma.sync tf32 GEMM: C[M,N] = f(A @ Bt^T + bias) (+res)
//   128x128 tile, BK=32, 8 warps (2x4), 64x32 per warp, double-buffered cp.async
//   2 CTAs/SM (regs capped to 128)
// ---------------------------------------------------------------------------
#define ASTRIDE 36
#define AB0 0
#define AB1 4608
#define BB0 9216
#define BB1 13824
#define GEMM_SMEM (18432 * 4)

template<bool SILU, bool RES, bool ROUND>
__global__ void __launch_bounds__(256, 2)
gemm_mma(const float* __restrict__ A, const float* __restrict__ Bt,
         const float* __restrict__ bias, const float* __restrict__ res,
         float* __restrict__ C, int M, int N, int K)
{
    extern __shared__ float sm[];
    uint32_t sbase = smem_u32(sm);
    int tid = threadIdx.x;
    int wid = tid >> 5, lane = tid & 31;
    int g = lane >> 2, t = lane & 3;
    int wm = wid >> 2, wn = wid & 3;
    int bm = blockIdx.y * 128, bn = blockIdx.x * 128;
    const int NC = K >> 5;

    float c[4][4][4];
    #pragma unroll
    for (int i = 0; i < 4; i++)
        #pragma unroll
        for (int j = 0; j < 4; j++)
            #pragma unroll
            for (int e = 0; e < 4; e++) c[i][j][e] = 0.0f;

    auto load_tile = [&](int koff, int buf) {
        uint32_t ab = sbase + (buf ? AB1 : AB0) * 4;
        uint32_t bb = sbase + (buf ? BB1 : BB0) * 4;
        #pragma unroll
        for (int p = 0; p < 4; p++) {
            int idx = tid + p * 256;
            int row = idx >> 3, q = idx & 7;
            CP_ASYNC16(ab + row * 144 + q * 16,
                       A + (size_t)(bm + row) * K + koff + q * 4);
        }
        #pragma unroll
        for (int p = 0; p < 4; p++) {
            int idx = tid + p * 256;
            int row = idx >> 3, q = idx & 7;
            CP_ASYNC16(bb + row * 144 + q * 16,
                       Bt + (size_t)(bn + row) * K + koff + q * 4);
        }
        CP_COMMIT();
    };

    load_tile(0, 0);

    for (int i = 0; i < NC; i++) {
        if (i + 1 < NC) { load_tile((i + 1) << 5, (i + 1) & 1); CP_WAIT1(); }
        else            { CP_WAIT0(); }
        __syncthreads();

        const float* As = sm + ((i & 1) ? AB1 : AB0);
        const float* Bs = sm + ((i & 1) ? BB1 : BB0);

        #pragma unroll
        for (int k8 = 0; k8 < 4; k8++) {
            int kk = k8 * 8;
            uint32_t a[4][4], b[4][2];
            #pragma unroll
            for (int mt = 0; mt < 4; mt++) {
                const float* ap = As + (wm * 64 + mt * 16 + g) * ASTRIDE + kk + t;
                a[mt][0] = __float_as_uint(ap[0]);
                a[mt][1] = __float_as_uint(ap[8 * ASTRIDE]);
                a[mt][2] = __float_as_uint(ap[4]);
                a[mt][3] = __float_as_uint(ap[8 * ASTRIDE + 4]);
            }
            #pragma unroll
            for (int nt = 0; nt < 4; nt++) {
                const float* bp = Bs + (wn * 32 + nt * 8 + g) * ASTRIDE + kk + t;
                b[nt][0] = __float_as_uint(bp[0]);
                b[nt][1] = __float_as_uint(bp[4]);
            }
            #pragma unroll
            for (int mt = 0; mt < 4; mt++)
                #pragma unroll
                for (int nt = 0; nt < 4; nt++)
                    mma_tf32(c[mt][nt], a[mt], b[nt]);
        }
        __syncthreads();
    }

    // epilogue: register -> global (float2 pairs), bias/silu/residual fused
    #pragma unroll
    for (int mt = 0; mt < 4; mt++) {
        int r0 = bm + wm * 64 + mt * 16 + g;
        #pragma unroll
        for (int nt = 0; nt < 4; nt++) {
            int col = bn + wn * 32 + nt * 8 + 2 * t;
            float bx = 0.f, by = 0.f;
            if (bias) { bx = __ldg(bias + col); by = __ldg(bias + col + 1); }
            #pragma unroll
            for (int half = 0; half < 2; half++) {
                int r = r0 + half * 8;
                float vx = c[mt][nt][half * 2 + 0] + bx;
                float vy = c[mt][nt][half * 2 + 1] + by;
                if (SILU) {
                    vx = vx / (1.0f + __expf(-vx));
                    vy = vy / (1.0f + __expf(-vy));
                }
                if (RES) {
                    float2 rr = *(const float2*)(res + (size_t)r * N + col);
                    vx += rr.x; vy += rr.y;
                }
                if (ROUND) { vx = tf32_rna(vx); vy = tf32_rna(vy); }
                *(float2*)(C + (size_t)r * N + col) = make_float2(vx, vy);
            }
        }
    }
}

// ---------------------------------------------------------------------------
// SiLU attention, mma.sync tf32, double-buffered cp.async K/V.
// g_mix is pre-rounded to tf32 (GEMM1 epilogue), so loads go straight to smem.
// Computes S^T = K @ Q^T, then O = P @ V.
// smem (floats): KS0[64][68] KS1 VS0[64][72] VS1 QT[64][72] PS[64][68]
// ---------------------------------------------------------------------------
#define KS0_F 0
#define KS1_F 4352
#define VS0_F 8704
#define VS1_F 13312
#define QT_F  17920
#define PS_F  22528
#define ATT_SMEM (26880 * 4)   // 107520 B

__global__ void __launch_bounds__(256, 2) attn_mma()
{
    extern __shared__ float sm[];
    uint32_t sbase = smem_u32(sm);
    int bi = blockIdx.x, h = blockIdx.y, b = blockIdx.z;
    int tid = threadIdx.x, wid = tid >> 5, lane = tid & 31;
    int g = lane >> 2, t = lane & 3;
    int wj = wid >> 1, wi = wid & 1;
    const int qoff = 1024 + h * 64;
    const int koff = 1536 + h * 64;
    const int voff = 512  + h * 64;
    const int ibase = bi * 64;
    const size_t rowb = (size_t)b * SS;
    const float invS = 1.0f / (float)SS;

    auto load_kv = [&](int jbase, int buf) {
        uint32_t kb = sbase + (buf ? KS1_F : KS0_F) * 4;
        uint32_t vb = sbase + (buf ? VS1_F : VS0_F) * 4;
        #pragma unroll
        for (int p = 0; p < 4; p++) {
            int idx = tid + p * 256;
            int j = idx >> 4, d16 = idx & 15;
            const float* src = g_mix + (rowb + jbase + j) * (size_t)N4;
            CP_ASYNC16(kb + j * 272 + d16 * 16, src + koff + d16 * 4);
            CP_ASYNC16(vb + j * 288 + d16 * 16, src + voff + d16 * 4);
        }
        CP_COMMIT();
    };

    // prefetch tile 0 first, then Q^T (pre-rounded) transposed into smem
    load_kv(0, 0);
    for (int idx = tid; idx < 4096; idx += 256) {
        int i = idx >> 6, d = idx & 63;
        sm[QT_F + d * 72 + i] = g_mix[(rowb + ibase + i) * N4 + qoff + d];
    }

    float o[4][4];
    #pragma unroll
    for (int nt = 0; nt < 4; nt++)
        #pragma unroll
        for (int e = 0; e < 4; e++) o[nt][e] = 0.0f;

    for (int jt = 0; jt <= bi; jt++) {
        int jbase = jt * 64;
        int cur = jt & 1;
        const float* Ks = sm + (cur ? KS1_F : KS0_F);
        const float* Vs = sm + (cur ? VS1_F : VS0_F);

        CP_WAIT0();
        __syncthreads();   // K/V[cur] landed; all warps done with prev PV

        // S^T tile: rows j (wj*16), cols i (wi*32, 4 n-tiles)
        float c[4][4];
        #pragma unroll
        for (int nt = 0; nt < 4; nt++)
            #pragma unroll
            for (int e = 0; e < 4; e++) c[nt][e] = 0.0f;

        #pragma unroll
        for (int k8 = 0; k8 < 8; k8++) {
            int kk = k8 * 8;
            uint32_t a[4], bfr[4][2];
            const float* ap = Ks + (wj * 16 + g) * 68 + kk + t;
            a[0] = __float_as_uint(ap[0]);
            a[1] = __float_as_uint(ap[8 * 68]);
            a[2] = __float_as_uint(ap[4]);
            a[3] = __float_as_uint(ap[8 * 68 + 4]);
            #pragma unroll
            for (int nt = 0; nt < 4; nt++) {
                const float* bp = sm + QT_F + (kk + t) * 72 + wi * 32 + nt * 8 + g;
                bfr[nt][0] = __float_as_uint(bp[0]);
                bfr[nt][1] = __float_as_uint(bp[4 * 72]);
            }
            #pragma unroll
            for (int nt = 0; nt < 4; nt++)
                mma_tf32(c[nt], a, bfr[nt]);
        }

        // silu + mask (diagonal tile only), store P[i][j]
        bool diag = (jt == bi);
        #pragma unroll
        for (int nt = 0; nt < 4; nt++) {
            #pragma unroll
            for (int e = 0; e < 4; e++) {
                int jl = wj * 16 + g + ((e >> 1) * 8);
                int il = wi * 32 + nt * 8 + 2 * t + (e & 1);
                float z = c[nt][e] * ALPHA;
                float sv = z / (1.0f + __expf(-z)) * invS;
                if (diag) {
                    int gj = jbase + jl, gi = ibase + il;
                    bool valid = (gj <= gi) && ((gj < SS - NT) || (gi == gj));
                    sv = valid ? sv : 0.0f;
                }
                sm[PS_F + il * 68 + jl] = tf32_rna(sv);
            }
        }
        __syncthreads();   // Ps visible; Ks[cur] reads finished

        // prefetch next tile into the other buffer (overlaps PV below)
        if (jt < bi) load_kv(jbase + 64, cur ^ 1);

        // O += P @ V : rows i (wj*16), cols d (wi*32, 4 n-tiles), k = j (64)
        #pragma unroll
        for (int k8 = 0; k8 < 8; k8++) {
            int kk = k8 * 8;
            uint32_t a[4], bfr[4][2];
            const float* ap = sm + PS_F + (wj * 16 + g) * 68 + kk + t;
            a[0] = __float_as_uint(ap[0]);
            a[1] = __float_as_uint(ap[8 * 68]);
            a[2] = __float_as_uint(ap[4]);
            a[3] = __float_as_uint(ap[8 * 68 + 4]);
            #pragma unroll
            for (int nt = 0; nt < 4; nt++) {
                const float* bp = Vs + (kk + t) * 72 + wi * 32 + nt * 8 + g;
                bfr[nt][0] = __float_as_uint(bp[0]);
                bfr[nt][1] = __float_as_uint(bp[4 * 72]);
            }
            #pragma unroll
            for (int nt = 0; nt < 4; nt++)
                mma_tf32(o[nt], a, bfr[nt]);
        }
    }

    // write attn_out
    #pragma unroll
    for (int nt = 0; nt < 4; nt++) {
        int col = h * 64 + wi * 32 + nt * 8 + 2 * t;
        #pragma unroll
        for (int half = 0; half < 2; half++) {
            size_t r = rowb + ibase + wj * 16 + g + half * 8;
            *(float2*)(g_att + r * EE + col) =
                make_float2(o[nt][half * 2 + 0], o[nt][half * 2 + 1]);
        }
    }
}

// ---------------------------------------------------------------------------
extern "C" void kernel_launch(void* const* d_in, const int* in_sizes, int n_in,
                              void* d_out, int out_size)
{
    const float* x       = (const float*)d_in[0];
    const float* w_uvqk  = (const float*)d_in[1];
    const float* b_uvqk  = (const float*)d_in[2];
    const float* ln_in_w = (const float*)d_in[3];
    const float* ln_in_b = (const float*)d_in[4];
    const float* ln_o_w  = (const float*)d_in[5];
    const float* ln_o_b  = (const float*)d_in[6];
    const float* w_proj  = (const float*)d_in[7];
    float* out = (float*)d_out;

    float *xn, *mix, *att, *par, *wuT, *wpT;
    cudaGetSymbolAddress((void**)&xn,  g_xn);
    cudaGetSymbolAddress((void**)&mix, g_mix);
    cudaGetSymbolAddress((void**)&att, g_att);
    cudaGetSymbolAddress((void**)&par, g_par);
    cudaGetSymbolAddress((void**)&wuT, g_wuT);
    cudaGetSymbolAddress((void**)&wpT, g_wpT);

    cudaFuncSetAttribute(gemm_mma<true, false, true>,
                         cudaFuncAttributeMaxDynamicSharedMemorySize, GEMM_SMEM);
    cudaFuncSetAttribute(gemm_mma<false, true, false>,
                         cudaFuncAttributeMaxDynamicSharedMemorySize, GEMM_SMEM);
    cudaFuncSetAttribute(attn_mma,
                         cudaFuncAttributeMaxDynamicSharedMemorySize, ATT_SMEM);

    // weight transposes (tf32-rounded)
    {
        dim3 b32(32, 8);
        transpose_kernel<<<dim3(N4 / 32, EE / 32), b32>>>(w_uvqk, wuT, EE, N4);
        transpose_kernel<<<dim3(EE / 32, EE / 32), b32>>>(w_proj, wpT, EE, EE);
    }

    // 1) input LN
    ln_in_kernel<<<TT, 128>>>(x, ln_in_w, ln_in_b, xn);

    // 2) mixed = silu(xn @ w_uvqk + b)  -> tf32-rounded
    {
        dim3 grid(N4 / 128, TT / 128);
        gemm_mma<true, false, true><<<grid, 256, GEMM_SMEM>>>(xn, wuT, b_uvqk,
                                                              nullptr, mix,
                                                              TT, N4, EE);
    }

    // 3) attention
    {
        dim3 grid(SS / 64, HH, BB);
        attn_mma<<<grid, 256, ATT_SMEM>>>();
    }

    // 4) parallel = u * LN(attn_out)
    ln_mul_kernel<<<TT, 128>>>(att, ln_o_w, ln_o_b, par);

    // 5) out = parallel @ w_proj + x
    {
        dim3 grid(EE / 128, TT / 128);
        gemm_mma<false, true, false><<<grid, 256, GEMM_SMEM>>>(par, wpT, nullptr,
                                                               x, out, TT, EE, EE);
    }
}

// round 8
// speedup vs baseline: 3.7230x; 1.0852x over previous
#include <cuda_runtime.h>
#include <math.h>
#include <stdint.h>

// Problem constants (fixed: B=8, S=2048, H=8, D=64)
#define TT   16384
#define EE   512
#define HH   8
#define SS   2048
#define BB   8
#define NT   64
#define N4   2048
#define ALPHA 0.125f

// Scratch
__device__ float g_xn  [TT * EE];
__device__ float g_mix [TT * N4];
__device__ float g_att [TT * EE];
__device__ float g_par [TT * EE];
__device__ float g_wuT [N4 * EE];
__device__ float g_wpT [EE * EE];
__device__ float g_vT  [BB * HH * 64 * SS];   // V transposed: [(b,h,d)][s]

// ---------------------------------------------------------------------------
__device__ __forceinline__ uint32_t smem_u32(const void* p) {
    uint32_t a;
    asm("{ .reg .u64 t; cvta.to.shared.u64 t, %1; cvt.u32.u64 %0, t; }"
        : "=r"(a) : "l"(p));
    return a;
}
__device__ __forceinline__ float tf32_rna(float x) {
    uint32_t u = __float_as_uint(x);
    asm("cvt.rna.tf32.f32 %0, %1;" : "=r"(u) : "r"(u));
    return __uint_as_float(u);
}
__device__ __forceinline__ void mma_tf32(float* c, const uint32_t* a, const uint32_t* b) {
    asm volatile(
        "mma.sync.aligned.m16n8k8.row.col.f32.tf32.tf32.f32 "
        "{%0,%1,%2,%3}, {%4,%5,%6,%7}, {%8,%9}, {%0,%1,%2,%3};"
        : "+f"(c[0]), "+f"(c[1]), "+f"(c[2]), "+f"(c[3])
        : "r"(a[0]), "r"(a[1]), "r"(a[2]), "r"(a[3]), "r"(b[0]), "r"(b[1]));
}
// One x4 ldmatrix: 4 8x8 b16 matrices == 4 8x4 tf32 quadrants
__device__ __forceinline__ void ldsm_x4(uint32_t& r0, uint32_t& r1,
                                        uint32_t& r2, uint32_t& r3, uint32_t addr) {
    asm volatile("ldmatrix.sync.aligned.m8n8.x4.shared.b16 {%0,%1,%2,%3}, [%4];"
                 : "=r"(r0), "=r"(r1), "=r"(r2), "=r"(r3) : "r"(addr));
}
#define CP_ASYNC16(s, g) asm volatile("cp.async.cg.shared.global [%0], [%1], 16;" :: "r"(s), "l"(g))
#define CP_COMMIT()      asm volatile("cp.async.commit_group;")
#define CP_WAIT1()       asm volatile("cp.async.wait_group 1;" ::: "memory")
#define CP_WAIT0()       asm volatile("cp.async.wait_group 0;" ::: "memory")

// A-fragment ldmatrix lane-address offset (bytes), stride in floats.
// Quadrants: m0=[r 0-7][k 0-3], m1=[r 8-15][k 0-3], m2=[r 0-7][k 4-7], m3=[r 8-15][k 4-7]
__device__ __forceinline__ uint32_t lda_off(int baserow, int stride, int lane) {
    int r15 = lane & 15, c4 = (lane >> 4) * 4;
    return (uint32_t)(((baserow + r15) * stride + c4) * 4);
}
// B-fragment pair (two adjacent 8-col n-tiles): m0=[n 0-7][k0-3], m1=[n 0-7][k4-7],
// m2=[n 8-15][k0-3], m3=[n 8-15][k4-7]
__device__ __forceinline__ uint32_t ldb_off(int baserow, int stride, int lane) {
    int r7 = lane & 7, sel = lane >> 3;
    return (uint32_t)(((baserow + r7 + (sel >> 1) * 8) * stride + (sel & 1) * 4) * 4);
}

// ---------------------------------------------------------------------------
// Weight transpose + tf32 rounding: dst[n][k] = rna(src[k][n])
// ---------------------------------------------------------------------------
__global__ void transpose_kernel(const float* __restrict__ src,
                                 float* __restrict__ dst, int K, int N)
{
    __shared__ float t[32][33];
    int n0 = blockIdx.x * 32, k0 = blockIdx.y * 32;
    int tx = threadIdx.x, ty = threadIdx.y;
    #pragma unroll
    for (int j = 0; j < 4; j++)
        t[ty + j * 8][tx] = src[(size_t)(k0 + ty + j * 8) * N + n0 + tx];
    __syncthreads();
    #pragma unroll
    for (int j = 0; j < 4; j++)
        dst[(size_t)(n0 + ty + j * 8) * K + k0 + tx] = tf32_rna(t[tx][ty + j * 8]);
}

// v transpose: g_vT[(b*H+h)*64 + d][s] = g_mix[b*S+s][512 + h*64 + d]
__global__ void vt_kernel()
{
    __shared__ float t[32][33];
    int bh = blockIdx.z;
    int s0 = blockIdx.x * 32, d0 = blockIdx.y * 32;
    int tx = threadIdx.x, ty = threadIdx.y;
    int b = bh >> 3, h = bh & 7;
    #pragma unroll
    for (int j = 0; j < 4; j++)
        t[ty + j * 8][tx] =
            g_mix[(size_t)(b * SS + s0 + ty + j * 8) * N4 + 512 + h * 64 + d0 + tx];
    __syncthreads();
    #pragma unroll
    for (int j = 0; j < 4; j++)
        g_vT[(size_t)(bh * 64 + d0 + ty + j * 8) * SS + s0 + tx] = t[tx][ty + j * 8];
}

// ---------------------------------------------------------------------------
// LayerNorm kernels (tf32-rounded outputs)
// ---------------------------------------------------------------------------
__global__ void ln_in_kernel(const float* __restrict__ x,
                             const float* __restrict__ w,
                             const float* __restrict__ b,
                             float* __restrict__ out)
{
    int row = blockIdx.x;
    int tid = threadIdx.x;
    const float4* xr = (const float4*)(x + (size_t)row * EE);
    float4 v = xr[tid];
    float s  = v.x + v.y + v.z + v.w;
    float s2 = v.x*v.x + v.y*v.y + v.z*v.z + v.w*v.w;
    #pragma unroll
    for (int off = 16; off; off >>= 1) {
        s  += __shfl_xor_sync(0xffffffffu, s,  off);
        s2 += __shfl_xor_sync(0xffffffffu, s2, off);
    }
    __shared__ float sb[4], sb2[4];
    int wid = tid >> 5, lane = tid & 31;
    if (lane == 0) { sb[wid] = s; sb2[wid] = s2; }
    __syncthreads();
    float tot  = sb[0] + sb[1] + sb[2] + sb[3];
    float tot2 = sb2[0] + sb2[1] + sb2[2] + sb2[3];
    float mu  = tot * (1.0f / EE);
    float var = tot2 * (1.0f / EE) - mu * mu;
    float rstd = rsqrtf(var + 1e-5f);
    float4 w4 = ((const float4*)w)[tid];
    float4 b4 = ((const float4*)b)[tid];
    float4 o;
    o.x = tf32_rna((v.x - mu) * rstd * w4.x + b4.x);
    o.y = tf32_rna((v.y - mu) * rstd * w4.y + b4.y);
    o.z = tf32_rna((v.z - mu) * rstd * w4.z + b4.z);
    o.w = tf32_rna((v.w - mu) * rstd * w4.w + b4.w);
    ((float4*)(out + (size_t)row * EE))[tid] = o;
}

__global__ void ln_mul_kernel(const float* __restrict__ a,
                              const float* __restrict__ w,
                              const float* __restrict__ b,
                              float* __restrict__ out)
{
    int row = blockIdx.x;
    int tid = threadIdx.x;
    const float4* xr = (const float4*)(a + (size_t)row * EE);
    float4 v = xr[tid];
    float s  = v.x + v.y + v.z + v.w;
    float s2 = v.x*v.x + v.y*v.y + v.z*v.z + v.w*v.w;
    #pragma unroll
    for (int off = 16; off; off >>= 1) {
        s  += __shfl_xor_sync(0xffffffffu, s,  off);
        s2 += __shfl_xor_sync(0xffffffffu, s2, off);
    }
    __shared__ float sb[4], sb2[4];
    int wid = tid >> 5, lane = tid & 31;
    if (lane == 0) { sb[wid] = s; sb2[wid] = s2; }
    __syncthreads();
    float tot  = sb[0] + sb[1] + sb[2] + sb[3];
    float tot2 = sb2[0] + sb2[1] + sb2[2] + sb2[3];
    float mu  = tot * (1.0f / EE);
    float var = tot2 * (1.0f / EE) - mu * mu;
    float rstd = rsqrtf(var + 1e-5f);
    float4 w4 = ((const float4*)w)[tid];
    float4 b4 = ((const float4*)b)[tid];
    float4 u4 = ((const float4*)(g_mix + (size_t)row * N4))[tid];
    float4 o;
    o.x = tf32_rna(u4.x * ((v.x - mu) * rstd * w4.x + b4.x));
    o.y = tf32_rna(u4.y * ((v.y - mu) * rstd * w4.y + b4.y));
    o.z = tf32_rna(u4.z * ((v.z - mu) * rstd * w4.z + b4.z));
    o.w = tf32_rna(u4.w * ((v.w - mu) * rstd * w4.w + b4.w));
    ((float4*)(out + (size_t)row * EE))[tid] = o;
}

// ---------------------------------------------------------------------------
// mma.sync tf32 GEMM, ldmatrix fragment feed.
//   128x128 tile, BK=32, 8 warps (2x4), 64x32 per warp, double-buffered cp.async
// ---------------------------------------------------------------------------
#define ASTRIDE 36
#define AB0 0
#define AB1 4608
#define BB0 9216
#define BB1 13824
#define GEMM_SMEM (18432 * 4)

template<bool SILU, bool RES, bool ROUND>
__global__ void __launch_bounds__(256, 2)
gemm_mma(const float* __restrict__ A, const float* __restrict__ Bt,
         const float* __restrict__ bias, const float* __restrict__ res,
         float* __restrict__ C, int M, int N, int K)
{
    extern __shared__ float sm[];
    uint32_t sbase = smem_u32(sm);
    int tid = threadIdx.x;
    int wid = tid >> 5, lane = tid & 31;
    int g = lane >> 2, t = lane & 3;
    int wm = wid >> 2, wn = wid & 3;
    int bm = blockIdx.y * 128, bn = blockIdx.x * 128;
    const int NC = K >> 5;

    // ldmatrix lane offsets (bytes, relative to buffer base)
    uint32_t aoff[4], boff[2];
    #pragma unroll
    for (int mt = 0; mt < 4; mt++)
        aoff[mt] = lda_off(wm * 64 + mt * 16, ASTRIDE, lane);
    boff[0] = ldb_off(wn * 32,      ASTRIDE, lane);
    boff[1] = ldb_off(wn * 32 + 16, ASTRIDE, lane);

    float c[4][4][4];
    #pragma unroll
    for (int i = 0; i < 4; i++)
        #pragma unroll
        for (int j = 0; j < 4; j++)
            #pragma unroll
            for (int e = 0; e < 4; e++) c[i][j][e] = 0.0f;

    auto load_tile = [&](int koff, int buf) {
        uint32_t ab = sbase + (buf ? AB1 : AB0) * 4;
        uint32_t bb = sbase + (buf ? BB1 : BB0) * 4;
        #pragma unroll
        for (int p = 0; p < 4; p++) {
            int idx = tid + p * 256;
            int row = idx >> 3, q = idx & 7;
            CP_ASYNC16(ab + row * 144 + q * 16,
                       A + (size_t)(bm + row) * K + koff + q * 4);
        }
        #pragma unroll
        for (int p = 0; p < 4; p++) {
            int idx = tid + p * 256;
            int row = idx >> 3, q = idx & 7;
            CP_ASYNC16(bb + row * 144 + q * 16,
                       Bt + (size_t)(bn + row) * K + koff + q * 4);
        }
        CP_COMMIT();
    };

    load_tile(0, 0);

    for (int i = 0; i < NC; i++) {
        if (i + 1 < NC) { load_tile((i + 1) << 5, (i + 1) & 1); CP_WAIT1(); }
        else            { CP_WAIT0(); }
        __syncthreads();

        uint32_t abuf = sbase + ((i & 1) ? AB1 : AB0) * 4;
        uint32_t bbuf = sbase + ((i & 1) ? BB1 : BB0) * 4;

        #pragma unroll
        for (int k8 = 0; k8 < 4; k8++) {
            uint32_t kb = k8 * 32;    // 8 floats
            uint32_t a[4][4], b[4][2];
            #pragma unroll
            for (int mt = 0; mt < 4; mt++)
                ldsm_x4(a[mt][0], a[mt][1], a[mt][2], a[mt][3],
                        abuf + aoff[mt] + kb);
            ldsm_x4(b[0][0], b[0][1], b[1][0], b[1][1], bbuf + boff[0] + kb);
            ldsm_x4(b[2][0], b[2][1], b[3][0], b[3][1], bbuf + boff[1] + kb);
            #pragma unroll
            for (int mt = 0; mt < 4; mt++)
                #pragma unroll
                for (int nt = 0; nt < 4; nt++)
                    mma_tf32(c[mt][nt], a[mt], b[nt]);
        }
        __syncthreads();
    }

    // epilogue
    #pragma unroll
    for (int mt = 0; mt < 4; mt++) {
        int r0 = bm + wm * 64 + mt * 16 + g;
        #pragma unroll
        for (int nt = 0; nt < 4; nt++) {
            int col = bn + wn * 32 + nt * 8 + 2 * t;
            float bx = 0.f, by = 0.f;
            if (bias) { bx = __ldg(bias + col); by = __ldg(bias + col + 1); }
            #pragma unroll
            for (int half = 0; half < 2; half++) {
                int r = r0 + half * 8;
                float vx = c[mt][nt][half * 2 + 0] + bx;
                float vy = c[mt][nt][half * 2 + 1] + by;
                if (SILU) {
                    vx = vx / (1.0f + __expf(-vx));
                    vy = vy / (1.0f + __expf(-vy));
                }
                if (RES) {
                    float2 rr = *(const float2*)(res + (size_t)r * N + col);
                    vx += rr.x; vy += rr.y;
                }
                if (ROUND) { vx = tf32_rna(vx); vy = tf32_rna(vy); }
                *(float2*)(C + (size_t)r * N + col) = make_float2(vx, vy);
            }
        }
    }
}

// ---------------------------------------------------------------------------
// SiLU attention, ldmatrix everywhere, double-buffered cp.async K/V^T.
// Computes S^T = K @ Q^T (row-major Qs feeds B-frags directly), O = P @ V
// with V^T pre-transposed (g_vT) so PV B-frags are also ldmatrix.
// smem (floats, stride 68): KS0 KS1 VT0 VT1 QS PS, each 64x68
// ---------------------------------------------------------------------------
#define KS0_F 0
#define KS1_F 4352
#define VT0_F 8704
#define VT1_F 13056
#define QS_F  17408
#define PS_F  21760
#define ATT_SMEM (26112 * 4)   // 104448 B; 2 CTAs/SM = 204 KB

__global__ void __launch_bounds__(256, 2) attn_mma()
{
    extern __shared__ float sm[];
    uint32_t sbase = smem_u32(sm);
    int bi = gridDim.x - 1 - blockIdx.x;   // longest CTAs first
    int h = blockIdx.y, b = blockIdx.z;
    int tid = threadIdx.x, wid = tid >> 5, lane = tid & 31;
    int g = lane >> 2, t = lane & 3;
    int wj = wid >> 1, wi = wid & 1;
    const int qoff = 1024 + h * 64;
    const int koff = 1536 + h * 64;
    const int ibase = bi * 64;
    const size_t rowb = (size_t)b * SS;
    const size_t vtb  = (size_t)(b * HH + h) * 64;
    const float invS = 1.0f / (float)SS;

    // ldmatrix lane offsets (bytes)
    uint32_t a_qk = lda_off(wj * 16, 68, lane);     // from Ks
    uint32_t a_pv = lda_off(wj * 16, 68, lane);     // from Ps (same shape)
    uint32_t b0off = ldb_off(wi * 32,      68, lane);
    uint32_t b1off = ldb_off(wi * 32 + 16, 68, lane);

    auto load_kv = [&](int jbase, int buf) {
        uint32_t kb = sbase + (buf ? KS1_F : KS0_F) * 4;
        uint32_t vb = sbase + (buf ? VT1_F : VT0_F) * 4;
        #pragma unroll
        for (int p = 0; p < 4; p++) {
            int idx = tid + p * 256;
            int row = idx >> 4, c16 = idx & 15;
            CP_ASYNC16(kb + row * 272 + c16 * 16,
                       g_mix + (rowb + jbase + row) * (size_t)N4 + koff + c16 * 4);
            CP_ASYNC16(vb + row * 272 + c16 * 16,
                       g_vT + (vtb + row) * SS + jbase + c16 * 4);
        }
        CP_COMMIT();
    };

    // prefetch tile 0, then Q (row-major, pre-rounded tf32) via cp.async
    load_kv(0, 0);
    {
        uint32_t qb = sbase + QS_F * 4;
        #pragma unroll
        for (int p = 0; p < 4; p++) {
            int idx = tid + p * 256;
            int row = idx >> 4, c16 = idx & 15;
            CP_ASYNC16(qb + row * 272 + c16 * 16,
                       g_mix + (rowb + ibase + row) * (size_t)N4 + qoff + c16 * 4);
        }
        CP_COMMIT();
    }

    float o[4][4];
    #pragma unroll
    for (int nt = 0; nt < 4; nt++)
        #pragma unroll
        for (int e = 0; e < 4; e++) o[nt][e] = 0.0f;

    for (int jt = 0; jt <= bi; jt++) {
        int jbase = jt * 64;
        int cur = jt & 1;
        uint32_t ksb = sbase + (cur ? KS1_F : KS0_F) * 4;
        uint32_t vtb_s = sbase + (cur ? VT1_F : VT0_F) * 4;
        uint32_t qsb = sbase + QS_F * 4;
        uint32_t psb = sbase + PS_F * 4;

        CP_WAIT0();
        __syncthreads();   // K/V[cur]+Q landed; all warps done with prev PV

        // S^T tile: rows j (wj*16), cols i (wi*32, 4 n-tiles)
        float c[4][4];
        #pragma unroll
        for (int nt = 0; nt < 4; nt++)
            #pragma unroll
            for (int e = 0; e < 4; e++) c[nt][e] = 0.0f;

        #pragma unroll
        for (int k8 = 0; k8 < 8; k8++) {
            uint32_t kb = k8 * 32;
            uint32_t a[4], bfr[4][2];
            ldsm_x4(a[0], a[1], a[2], a[3], ksb + a_qk + kb);
            ldsm_x4(bfr[0][0], bfr[0][1], bfr[1][0], bfr[1][1], qsb + b0off + kb);
            ldsm_x4(bfr[2][0], bfr[2][1], bfr[3][0], bfr[3][1], qsb + b1off + kb);
            #pragma unroll
            for (int nt = 0; nt < 4; nt++)
                mma_tf32(c[nt], a, bfr[nt]);
        }

        // silu + mask (diagonal tile only), store P[i][j]
        bool diag = (jt == bi);
        #pragma unroll
        for (int nt = 0; nt < 4; nt++) {
            #pragma unroll
            for (int e = 0; e < 4; e++) {
                int jl = wj * 16 + g + ((e >> 1) * 8);
                int il = wi * 32 + nt * 8 + 2 * t + (e & 1);
                float z = c[nt][e] * ALPHA;
                float sv = z / (1.0f + __expf(-z)) * invS;
                if (diag) {
                    int gj = jbase + jl, gi = ibase + il;
                    bool valid = (gj <= gi) && ((gj < SS - NT) || (gi == gj));
                    sv = valid ? sv : 0.0f;
                }
                sm[PS_F + il * 68 + jl] = tf32_rna(sv);
            }
        }
        __syncthreads();   // Ps visible; Ks/Qs reads finished

        // prefetch next tile (overlaps PV)
        if (jt < bi) load_kv(jbase + 64, cur ^ 1);

        // O += P @ V : A from Ps, B from VTs (both ldmatrix)
        #pragma unroll
        for (int k8 = 0; k8 < 8; k8++) {
            uint32_t kb = k8 * 32;
            uint32_t a[4], bfr[4][2];
            ldsm_x4(a[0], a[1], a[2], a[3], psb + a_pv + kb);
            ldsm_x4(bfr[0][0], bfr[0][1], bfr[1][0], bfr[1][1], vtb_s + b0off + kb);
            ldsm_x4(bfr[2][0], bfr[2][1], bfr[3][0], bfr[3][1], vtb_s + b1off + kb);
            #pragma unroll
            for (int nt = 0; nt < 4; nt++)
                mma_tf32(o[nt], a, bfr[nt]);
        }
    }

    // write attn_out
    #pragma unroll
    for (int nt = 0; nt < 4; nt++) {
        int col = h * 64 + wi * 32 + nt * 8 + 2 * t;
        #pragma unroll
        for (int half = 0; half < 2; half++) {
            size_t r = rowb + ibase + wj * 16 + g + half * 8;
            *(float2*)(g_att + r * EE + col) =
                make_float2(o[nt][half * 2 + 0], o[nt][half * 2 + 1]);
        }
    }
}

// ---------------------------------------------------------------------------
extern "C" void kernel_launch(void* const* d_in, const int* in_sizes, int n_in,
                              void* d_out, int out_size)
{
    const float* x       = (const float*)d_in[0];
    const float* w_uvqk  = (const float*)d_in[1];
    const float* b_uvqk  = (const float*)d_in[2];
    const float* ln_in_w = (const float*)d_in[3];
    const float* ln_in_b = (const float*)d_in[4];
    const float* ln_o_w  = (const float*)d_in[5];
    const float* ln_o_b  = (const float*)d_in[6];
    const float* w_proj  = (const float*)d_in[7];
    float* out = (float*)d_out;

    float *xn, *mix, *att, *par, *wuT, *wpT;
    cudaGetSymbolAddress((void**)&xn,  g_xn);
    cudaGetSymbolAddress((void**)&mix, g_mix);
    cudaGetSymbolAddress((void**)&att, g_att);
    cudaGetSymbolAddress((void**)&par, g_par);
    cudaGetSymbolAddress((void**)&wuT, g_wuT);
    cudaGetSymbolAddress((void**)&wpT, g_wpT);

    cudaFuncSetAttribute(gemm_mma<true, false, true>,
                         cudaFuncAttributeMaxDynamicSharedMemorySize, GEMM_SMEM);
    cudaFuncSetAttribute(gemm_mma<false, true, false>,
                         cudaFuncAttributeMaxDynamicSharedMemorySize, GEMM_SMEM);
    cudaFuncSetAttribute(attn_mma,
                         cudaFuncAttributeMaxDynamicSharedMemorySize, ATT_SMEM);

    // weight transposes (tf32-rounded)
    {
        dim3 b32(32, 8);
        transpose_kernel<<<dim3(N4 / 32, EE / 32), b32>>>(w_uvqk, wuT, EE, N4);
        transpose_kernel<<<dim3(EE / 32, EE / 32), b32>>>(w_proj, wpT, EE, EE);
    }

    // 1) input LN
    ln_in_kernel<<<TT, 128>>>(x, ln_in_w, ln_in_b, xn);

    // 2) mixed = silu(xn @ w_uvqk + b)  -> tf32-rounded
    {
        dim3 grid(N4 / 128, TT / 128);
        gemm_mma<true, false, true><<<grid, 256, GEMM_SMEM>>>(xn, wuT, b_uvqk,
                                                              nullptr, mix,
                                                              TT, N4, EE);
    }

    // 2b) v transpose for attention PV ldmatrix
    {
        dim3 b32(32, 8);
        vt_kernel<<<dim3(SS / 32, 2, BB * HH), b32>>>();
    }

    // 3) attention
    {
        dim3 grid(SS / 64, HH, BB);
        attn_mma<<<grid, 256, ATT_SMEM>>>();
    }

    // 4) parallel = u * LN(attn_out)
    ln_mul_kernel<<<TT, 128>>>(att, ln_o_w, ln_o_b, par);

    // 5) out = parallel @ w_proj + x
    {
        dim3 grid(EE / 128, TT / 128);
        gemm_mma<false, true, false><<<grid, 256, GEMM_SMEM>>>(par, wpT, nullptr,
                                                               x, out, TT, EE, EE);
    }
}